// round 1
// baseline (speedup 1.0000x reference)
#include <cuda_runtime.h>
#include <math.h>

#define N_IN     12288
#define H0       256
#define B_TOT    8192
#define ROWS_PER_CTA 4
#define MAX_ACT  512

// Scratch: transposed feature weights [N_IN][H0] = 12.58 MB
__device__ float g_ftT[N_IN * H0];
// side dtype mode: 0 = int32, 1 = float32, 2 = byte(bool)
__device__ int g_side_mode;

// ---------------------------------------------------------------------------
// Kernel 1: detect the storage dtype of `side` (jax bool -> harness dtype).
// Scans first 8192 bytes (valid for int32[8192]=32KB, float32=32KB, uint8=8KB).
//   int32 0/1  : only bytes at pos%4==0 can be nonzero
//   float32 1.0: bytes [00 00 80 3F] -> pos%4 in {2,3} nonzero, {0,1} zero
//   uint8 0/1  : nonzeros spread across all pos%4
// ---------------------------------------------------------------------------
__global__ void detect_side_kernel(const unsigned char* __restrict__ p) {
    __shared__ int nz[4];
    if (threadIdx.x < 4) nz[threadIdx.x] = 0;
    __syncthreads();
    int local = 0;
    for (int i = threadIdx.x; i < 8192; i += 256) {
        if (p[i]) local = 1;
    }
    if (local) atomicOr(&nz[threadIdx.x & 3], 1);
    __syncthreads();
    if (threadIdx.x == 0) {
        int mode;
        if (!(nz[1] | nz[2] | nz[3]))       mode = 0;  // int32
        else if (!nz[0] && !nz[1])          mode = 1;  // float32
        else                                mode = 2;  // byte
        g_side_mode = mode;
    }
}

__device__ __forceinline__ bool read_side(const void* p, int r, int mode) {
    if (mode == 0) return ((const int*)p)[r] != 0;
    if (mode == 1) return ((const float*)p)[r] != 0.0f;
    return ((const unsigned char*)p)[r] != 0;
}

// ---------------------------------------------------------------------------
// Kernel 2: tiled transpose ft_w [H0, N_IN] -> g_ftT [N_IN, H0]
// ---------------------------------------------------------------------------
__global__ void transpose_ft_kernel(const float* __restrict__ ft_w) {
    __shared__ float tile[32][33];
    int j0 = blockIdx.x * 32;   // N_IN dim
    int h0 = blockIdx.y * 32;   // H0 dim
    int tx = threadIdx.x, ty = threadIdx.y;  // (32, 8)
    #pragma unroll
    for (int i = 0; i < 32; i += 8)
        tile[ty + i][tx] = ft_w[(size_t)(h0 + ty + i) * N_IN + j0 + tx];
    __syncthreads();
    #pragma unroll
    for (int i = 0; i < 32; i += 8)
        g_ftT[(size_t)(j0 + ty + i) * H0 + h0 + tx] = tile[tx][ty + i];
}

// ---------------------------------------------------------------------------
// Kernel 3: main NNUE evaluation. 256 threads/CTA, ROWS_PER_CTA rows per CTA.
// ---------------------------------------------------------------------------
__device__ __forceinline__ float clamp01(float x) {
    return fminf(fmaxf(x, 0.0f), 1.0f);
}

__global__ __launch_bounds__(256)
void nnue_kernel(const float* __restrict__ wf,
                 const float* __restrict__ bf,
                 const void*  __restrict__ side,
                 const float* __restrict__ ft_b,
                 const float* __restrict__ l1_w,
                 const float* __restrict__ l1_b,
                 const float* __restrict__ l2_w,
                 const float* __restrict__ l2_b,
                 const float* __restrict__ l3_w,
                 const float* __restrict__ l3_b,
                 float* __restrict__ out) {
    __shared__ int   s_idx[2][MAX_ACT];
    __shared__ int   s_cnt[2];
    __shared__ float s_o0[2 * H0];   // 512 combined clipped accumulator
    __shared__ float s_o1[32];

    const int t    = threadIdx.x;
    const int warp = t >> 5;
    const int lane = t & 31;
    const int mode = g_side_mode;
    const float bias = ft_b[t];

    for (int rr = 0; rr < ROWS_PER_CTA; rr++) {
        const int row = blockIdx.x * ROWS_PER_CTA + rr;
        if (t < 2) s_cnt[t] = 0;
        __syncthreads();

        // ---- scan both feature rows, collect active indices ----
        #pragma unroll
        for (int s = 0; s < 2; s++) {
            const float4* src = (const float4*)((s == 0 ? wf : bf) + (size_t)row * N_IN);
            #pragma unroll
            for (int i = 0; i < 12; i++) {
                float4 v = src[i * 256 + t];
                int base = (i * 256 + t) * 4;
                if (v.x != 0.0f) { int p = atomicAdd(&s_cnt[s], 1); if (p < MAX_ACT) s_idx[s][p] = base + 0; }
                if (v.y != 0.0f) { int p = atomicAdd(&s_cnt[s], 1); if (p < MAX_ACT) s_idx[s][p] = base + 1; }
                if (v.z != 0.0f) { int p = atomicAdd(&s_cnt[s], 1); if (p < MAX_ACT) s_idx[s][p] = base + 2; }
                if (v.w != 0.0f) { int p = atomicAdd(&s_cnt[s], 1); if (p < MAX_ACT) s_idx[s][p] = base + 3; }
            }
        }
        __syncthreads();
        const int nw = min(s_cnt[0], MAX_ACT);
        const int nb = min(s_cnt[1], MAX_ACT);

        // ---- accumulate ft columns: thread t owns hidden unit t ----
        float aw0 = 0.f, aw1 = 0.f, aw2 = 0.f, aw3 = 0.f;
        {
            int k = 0;
            for (; k + 4 <= nw; k += 4) {
                aw0 += g_ftT[(size_t)s_idx[0][k + 0] * H0 + t];
                aw1 += g_ftT[(size_t)s_idx[0][k + 1] * H0 + t];
                aw2 += g_ftT[(size_t)s_idx[0][k + 2] * H0 + t];
                aw3 += g_ftT[(size_t)s_idx[0][k + 3] * H0 + t];
            }
            for (; k < nw; k++) aw0 += g_ftT[(size_t)s_idx[0][k] * H0 + t];
        }
        float accw = bias + ((aw0 + aw1) + (aw2 + aw3));

        float ab0 = 0.f, ab1 = 0.f, ab2 = 0.f, ab3 = 0.f;
        {
            int k = 0;
            for (; k + 4 <= nb; k += 4) {
                ab0 += g_ftT[(size_t)s_idx[1][k + 0] * H0 + t];
                ab1 += g_ftT[(size_t)s_idx[1][k + 1] * H0 + t];
                ab2 += g_ftT[(size_t)s_idx[1][k + 2] * H0 + t];
                ab3 += g_ftT[(size_t)s_idx[1][k + 3] * H0 + t];
            }
            for (; k < nb; k++) ab0 += g_ftT[(size_t)s_idx[1][k] * H0 + t];
        }
        float accb = bias + ((ab0 + ab1) + (ab2 + ab3));

        // ---- perspective concat + clipped ReLU ----
        const bool sd = read_side(side, row, mode);
        s_o0[t]        = clamp01(sd ? accw : accb);
        s_o0[H0 + t]   = clamp01(sd ? accb : accw);
        __syncthreads();

        // ---- l1: 512 -> 32, warp-parallel dots (8 warps x 4 outputs) ----
        #pragma unroll
        for (int k4 = 0; k4 < 4; k4++) {
            const int o = warp + k4 * 8;
            const float* wrow = l1_w + (size_t)o * 512;
            float p = 0.f;
            #pragma unroll
            for (int j = 0; j < 16; j++)
                p += s_o0[lane + 32 * j] * wrow[lane + 32 * j];
            #pragma unroll
            for (int off = 16; off; off >>= 1)
                p += __shfl_down_sync(0xffffffffu, p, off);
            if (lane == 0) s_o1[o] = clamp01(p + l1_b[o]);
        }
        __syncthreads();

        // ---- l2: 32 -> 32, l3: 32 -> 1, sigmoid. warp 0 only. ----
        if (warp == 0) {
            float p = l2_b[lane];
            #pragma unroll
            for (int j = 0; j < 32; j++)
                p += s_o1[j] * l2_w[lane * 32 + j];
            float o2 = clamp01(p);
            float x = o2 * l3_w[lane];
            #pragma unroll
            for (int off = 16; off; off >>= 1)
                x += __shfl_down_sync(0xffffffffu, x, off);
            if (lane == 0) {
                float o3 = (x + l3_b[0]) * 300.0f;   // OUTPUT_SCALE
                out[row] = 1.0f / (1.0f + expf(-o3 / 200.0f));  // WDL_SCALE
            }
        }
        __syncthreads();
    }
}

// ---------------------------------------------------------------------------
// Launch
// ---------------------------------------------------------------------------
extern "C" void kernel_launch(void* const* d_in, const int* in_sizes, int n_in,
                              void* d_out, int out_size) {
    const float* wf    = (const float*)d_in[0];   // white_features [B, N_IN]
    const float* bf    = (const float*)d_in[1];   // black_features [B, N_IN]
    const void*  side  = d_in[2];                 // side [B] (dtype probed)
    const float* ft_w  = (const float*)d_in[3];   // [H0, N_IN]
    const float* ft_b  = (const float*)d_in[4];   // [H0]
    const float* l1_w  = (const float*)d_in[5];   // [32, 512]
    const float* l1_b  = (const float*)d_in[6];   // [32]
    const float* l2_w  = (const float*)d_in[7];   // [32, 32]
    const float* l2_b  = (const float*)d_in[8];   // [32]
    const float* l3_w  = (const float*)d_in[9];   // [1, 32]
    const float* l3_b  = (const float*)d_in[10];  // [1]
    float* out = (float*)d_out;

    detect_side_kernel<<<1, 256>>>((const unsigned char*)side);
    transpose_ft_kernel<<<dim3(N_IN / 32, H0 / 32), dim3(32, 8)>>>(ft_w);
    nnue_kernel<<<B_TOT / ROWS_PER_CTA, 256>>>(
        wf, bf, side, ft_b, l1_w, l1_b, l2_w, l2_b, l3_w, l3_b, out);
}

// round 5
// speedup vs baseline: 1.3798x; 1.3798x over previous
#include <cuda_runtime.h>
#include <math.h>

#define N_IN     12288
#define H0       256
#define B_TOT    8192
#define WARPS_PER_CTA 8
#define THREADS  (WARPS_PER_CTA * 32)
#define MAX_ACT  128

// Scratch (device globals; no allocation allowed)
__device__ float g_ftT[N_IN * H0];   // [feature][unit]  12.58 MB, L2-resident working set
__device__ float g_l1wB[32 * 512];   // packed: [jj][o][c] = l1_w[o][4*jj+c]  (jj=0..127)
__device__ float g_l2wT[32 * 32];    // [j][o] = l2_w[o][j]
__device__ int   g_side_mode;        // 0=int32, 1=float32, 2=byte

// ---------------------------------------------------------------------------
// Prep kernel (single launch): ft_w transpose + l1/l2 repack + side dtype probe
// blocks 0..3071: 32x32 transpose tiles; block 3072: misc
// ---------------------------------------------------------------------------
__global__ void prep_kernel(const float* __restrict__ ft_w,
                            const float* __restrict__ l1_w,
                            const float* __restrict__ l2_w,
                            const unsigned char* __restrict__ side) {
    __shared__ float tile[32][33];
    __shared__ unsigned s_acc;
    const int b = blockIdx.x;
    const int t = threadIdx.x;

    if (b < 3072) {
        const int bx = b % 384, by = b / 384;       // N_IN tiles x H0 tiles
        const int j0 = bx * 32, h0 = by * 32;
        const int tx = t & 31, ty = t >> 5;          // (32, 8)
        #pragma unroll
        for (int i = 0; i < 4; i++)
            tile[ty + i * 8][tx] = ft_w[(size_t)(h0 + ty + i * 8) * N_IN + j0 + tx];
        __syncthreads();
        #pragma unroll
        for (int i = 0; i < 4; i++)
            g_ftT[(size_t)(j0 + ty + i * 8) * H0 + h0 + tx] = tile[tx][ty + i * 8];
    } else {
        // l1 pack: [o][j] -> [jj][o][c]
        for (int e = t; e < 32 * 512; e += 256) {
            int o = e >> 9, j = e & 511;
            g_l1wB[(j >> 2) * 128 + o * 4 + (j & 3)] = l1_w[e];
        }
        // l2 transpose
        for (int e = t; e < 32 * 32; e += 256) {
            int o = e >> 5, j = e & 31;
            g_l2wT[j * 32 + o] = l2_w[e];
        }
        // side dtype probe: OR all 32-bit words of first 8192 bytes.
        // int32 0/1 -> byte0 only; float32 1.0f (0x3F800000) -> bytes 2,3 only;
        // uint8 bool -> low bytes of many words.
        if (t == 0) s_acc = 0;
        __syncthreads();
        const uint4* p4 = (const uint4*)side;
        unsigned a = 0;
        for (int i = t; i < 512; i += 256) {
            uint4 v = p4[i];
            a |= v.x | v.y | v.z | v.w;
        }
        atomicOr(&s_acc, a);
        __syncthreads();
        if (t == 0) {
            unsigned acc = s_acc;
            unsigned b0 = acc & 0xFFu, b1 = (acc >> 8) & 0xFFu;
            int mode;
            if (((acc >> 8) | 0u) == 0u || (b1 | (acc >> 16)) == 0u) mode = 0; // only byte0 set
            else if ((b0 | b1) == 0u)  mode = 1;   // float32 (bytes 2,3)
            else                       mode = 2;   // byte
            g_side_mode = mode;
        }
    }
}

// ---------------------------------------------------------------------------
// Main kernel: warp-per-row, no CTA barriers.
// ---------------------------------------------------------------------------
__device__ __forceinline__ float clamp01(float x) {
    return fminf(fmaxf(x, 0.0f), 1.0f);
}
__device__ __forceinline__ float4 add4(float4 a, float4 b) {
    a.x += b.x; a.y += b.y; a.z += b.z; a.w += b.w; return a;
}
__device__ __forceinline__ float4 clamp4(float4 a) {
    a.x = clamp01(a.x); a.y = clamp01(a.y); a.z = clamp01(a.z); a.w = clamp01(a.w);
    return a;
}

__global__ __launch_bounds__(THREADS)
void nnue_main(const float* __restrict__ wf,
               const float* __restrict__ bf,
               const void*  __restrict__ side,
               const float* __restrict__ ft_b,
               const float* __restrict__ l1_b,
               const float* __restrict__ l2_b,
               const float* __restrict__ l3_w,
               const float* __restrict__ l3_b,
               float* __restrict__ out) {
    __shared__ int   s_idx[WARPS_PER_CTA][2][MAX_ACT];
    __shared__ int   s_cnt[WARPS_PER_CTA][2];
    __shared__ float s_o0[WARPS_PER_CTA][512];
    __shared__ float s_o1[WARPS_PER_CTA][32];

    const int warp = threadIdx.x >> 5;
    const int lane = threadIdx.x & 31;
    const int row  = blockIdx.x * WARPS_PER_CTA + warp;
    const int mode = g_side_mode;
    if (row >= B_TOT) return;

    if (lane < 2) s_cnt[warp][lane] = 0;
    __syncwarp();

    // ---- scan: batches of 8 uint4 loads per lane (MLP=8), rare compaction ----
    #pragma unroll
    for (int s = 0; s < 2; s++) {
        const uint4* src = (const uint4*)((s == 0 ? wf : bf) + (size_t)row * N_IN);
        int* idx = s_idx[warp][s];
        for (int i = 0; i < 96; i += 8) {
            uint4 v[8];
            #pragma unroll
            for (int u = 0; u < 8; u++) v[u] = __ldg(&src[(i + u) * 32 + lane]);
            #pragma unroll
            for (int u = 0; u < 8; u++) {
                unsigned any = v[u].x | v[u].y | v[u].z | v[u].w;
                if (any) {
                    int n = (v[u].x != 0) + (v[u].y != 0) + (v[u].z != 0) + (v[u].w != 0);
                    int p = atomicAdd(&s_cnt[warp][s], n);
                    int base = ((i + u) * 32 + lane) << 2;
                    if (v[u].x && p < MAX_ACT) idx[p++] = base;
                    if (v[u].y && p < MAX_ACT) idx[p++] = base + 1;
                    if (v[u].z && p < MAX_ACT) idx[p++] = base + 2;
                    if (v[u].w && p < MAX_ACT) idx[p++] = base + 3;
                }
            }
        }
    }
    __syncwarp();
    const int nw = min(s_cnt[warp][0], MAX_ACT);
    const int nb = min(s_cnt[warp][1], MAX_ACT);

    // ---- gather from L2-resident g_ftT; lane owns 8 units (two float4 slices)
    const float4* ft4 = (const float4*)g_ftT;   // feature j starts at j*64 float4s
    float4 aw0 = __ldg(&((const float4*)ft_b)[lane]);
    float4 aw1 = __ldg(&((const float4*)ft_b)[32 + lane]);
    float4 ab0 = aw0, ab1 = aw1;
    {
        const int* idx = s_idx[warp][0];
        int k = 0;
        for (; k + 2 <= nw; k += 2) {
            const float4* f0 = ft4 + (size_t)idx[k] * 64;
            const float4* f1 = ft4 + (size_t)idx[k + 1] * 64;
            float4 x0 = f0[lane], x1 = f0[32 + lane];
            float4 y0 = f1[lane], y1 = f1[32 + lane];
            aw0 = add4(aw0, x0); aw1 = add4(aw1, x1);
            aw0 = add4(aw0, y0); aw1 = add4(aw1, y1);
        }
        if (k < nw) {
            const float4* f0 = ft4 + (size_t)idx[k] * 64;
            aw0 = add4(aw0, f0[lane]); aw1 = add4(aw1, f0[32 + lane]);
        }
    }
    {
        const int* idx = s_idx[warp][1];
        int k = 0;
        for (; k + 2 <= nb; k += 2) {
            const float4* f0 = ft4 + (size_t)idx[k] * 64;
            const float4* f1 = ft4 + (size_t)idx[k + 1] * 64;
            float4 x0 = f0[lane], x1 = f0[32 + lane];
            float4 y0 = f1[lane], y1 = f1[32 + lane];
            ab0 = add4(ab0, x0); ab1 = add4(ab1, x1);
            ab0 = add4(ab0, y0); ab1 = add4(ab1, y1);
        }
        if (k < nb) {
            const float4* f0 = ft4 + (size_t)idx[k] * 64;
            ab0 = add4(ab0, f0[lane]); ab1 = add4(ab1, f0[32 + lane]);
        }
    }

    // ---- perspective concat + clip, into per-warp shared ----
    bool sd;
    if (mode == 0)      sd = ((const int*)side)[row] != 0;
    else if (mode == 1) sd = ((const float*)side)[row] != 0.0f;
    else                sd = ((const unsigned char*)side)[row] != 0;

    float4* o04 = (float4*)s_o0[warp];
    o04[lane]      = clamp4(sd ? aw0 : ab0);
    o04[32 + lane] = clamp4(sd ? aw1 : ab1);
    o04[64 + lane] = clamp4(sd ? ab0 : aw0);
    o04[96 + lane] = clamp4(sd ? ab1 : aw1);
    __syncwarp();

    // ---- l1: 512 -> 32; lane = output o; packed coalesced weights ----
    float acc1 = 0.0f;
    {
        const float4* wB  = (const float4*)g_l1wB;     // [jj*32 + o]
        const float4* o0v = (const float4*)s_o0[warp];
        #pragma unroll 8
        for (int jj = 0; jj < 128; jj++) {
            float4 x = o0v[jj];
            float4 w = wB[jj * 32 + lane];
            acc1 = fmaf(x.x, w.x, acc1);
            acc1 = fmaf(x.y, w.y, acc1);
            acc1 = fmaf(x.z, w.z, acc1);
            acc1 = fmaf(x.w, w.w, acc1);
        }
    }
    s_o1[warp][lane] = clamp01(acc1 + __ldg(&l1_b[lane]));
    __syncwarp();

    // ---- l2: 32 -> 32, l3: 32 -> 1, sigmoid ----
    float q = __ldg(&l2_b[lane]);
    #pragma unroll
    for (int j = 0; j < 32; j++)
        q = fmaf(s_o1[warp][j], g_l2wT[j * 32 + lane], q);
    float o2 = clamp01(q);
    float x  = o2 * __ldg(&l3_w[lane]);
    #pragma unroll
    for (int off = 16; off; off >>= 1)
        x += __shfl_xor_sync(0xffffffffu, x, off);
    if (lane == 0)
        out[row] = 1.0f / (1.0f + expf(-(x + l3_b[0]) * 1.5f));  // *300/200
}

// ---------------------------------------------------------------------------
// Launch
// ---------------------------------------------------------------------------
extern "C" void kernel_launch(void* const* d_in, const int* in_sizes, int n_in,
                              void* d_out, int out_size) {
    const float* wf   = (const float*)d_in[0];
    const float* bf   = (const float*)d_in[1];
    const void*  side = d_in[2];
    const float* ft_w = (const float*)d_in[3];
    const float* ft_b = (const float*)d_in[4];
    const float* l1_w = (const float*)d_in[5];
    const float* l1_b = (const float*)d_in[6];
    const float* l2_w = (const float*)d_in[7];
    const float* l2_b = (const float*)d_in[8];
    const float* l3_w = (const float*)d_in[9];
    const float* l3_b = (const float*)d_in[10];
    float* out = (float*)d_out;

    prep_kernel<<<3073, 256>>>(ft_w, l1_w, l2_w, (const unsigned char*)side);
    nnue_main<<<B_TOT / WARPS_PER_CTA, THREADS>>>(
        wf, bf, side, ft_b, l1_b, l2_b, l3_w, l3_b, out);
}